// round 11
// baseline (speedup 1.0000x reference)
#include <cuda_runtime.h>
#include <cstdint>

// ---------------- problem constants ----------------
#define NB 4
#define NS 1024
#define ND 2048
#define NH 16
#define NQL 1536
#define NKVL 512
#define NNOPE 128
#define NROPE 64
#define NVH 128
#define NQKH 192
#define NM (NB*NS)          // 4096 token rows

// ---------------- scratch ----------------
__device__ float g_qd  [NM*NQL];
__device__ float g_qdn [NM*NQL];
__device__ float g_q   [NM*NH*NQKH];
__device__ float g_kv  [NM*(NKVL+NROPE)];
__device__ float g_kvn [NM*NKVL];
__device__ float g_kvu [NM*NH*(NNOPE+NVH)];
__device__ float g_krot[NM*NROPE];
__device__ float g_att [NM*NH*NVH];
// tf32-rounded copies (inputs to GEMMs)
__device__ float g_xtf [NM*ND];
__device__ float g_wqd [NQL*ND];
__device__ float g_wqu [NH*NQKH*NQL];
__device__ float g_wkv [(NKVL+NROPE)*ND];
__device__ float g_wkvu[NH*(NNOPE+NVH)*NKVL];
__device__ float g_wo  [ND*NH*NVH];

// ---------------- helpers ----------------
__device__ __forceinline__ uint32_t f2tf(float x) {
    uint32_t y;
    asm("cvt.rna.tf32.f32 %0, %1;" : "=r"(y) : "f"(x));
    return y;
}
__device__ __forceinline__ float f2tf_f(float x) { return __uint_as_float(f2tf(x)); }
__device__ __forceinline__ void split_tf(float x, uint32_t& hi, uint32_t& lo) {
    hi = f2tf(x);
    lo = f2tf(x - __uint_as_float(hi));
}
__device__ __forceinline__ void mma_tf32(float* c,
    uint32_t a0, uint32_t a1, uint32_t a2, uint32_t a3,
    uint32_t b0, uint32_t b1)
{
    asm volatile(
        "mma.sync.aligned.m16n8k8.row.col.f32.tf32.tf32.f32 "
        "{%0,%1,%2,%3}, {%4,%5,%6,%7}, {%8,%9}, {%0,%1,%2,%3};\n"
        : "+f"(c[0]), "+f"(c[1]), "+f"(c[2]), "+f"(c[3])
        : "r"(a0), "r"(a1), "r"(a2), "r"(a3), "r"(b0), "r"(b1));
}
__device__ __forceinline__ void cpasync16(uint32_t saddr, const void* g, uint32_t sz) {
    asm volatile("cp.async.cg.shared.global [%0], [%1], 16, %2;\n"
                 :: "r"(saddr), "l"(g), "r"(sz));
}
__device__ __forceinline__ void ldsm4(uint32_t& r0, uint32_t& r1, uint32_t& r2, uint32_t& r3,
                                      uint32_t addr)
{
    asm volatile("ldmatrix.sync.aligned.m8n8.x4.shared.b16 {%0,%1,%2,%3}, [%4];"
                 : "=r"(r0), "=r"(r1), "=r"(r2), "=r"(r3) : "r"(addr));
}

// ---------------- tf32 pre-round ----------------
__global__ __launch_bounds__(256) void tf32_round_kernel(
    const float* __restrict__ in, float* __restrict__ out, int n4)
{
    int i = blockIdx.x * 256 + threadIdx.x;
    if (i < n4) {
        float4 v = ((const float4*)in)[i];
        v.x = f2tf_f(v.x); v.y = f2tf_f(v.y); v.z = f2tf_f(v.z); v.w = f2tf_f(v.w);
        ((float4*)out)[i] = v;
    }
}

// ---------------- TF32 GEMM, cp.async double-buffered + ldmatrix fragments ----------------
#define TPAD 36
#define GSMEM (2 * 2 * 128 * TPAD * 4)   // 72 KB -> 2 CTAs/SM

__global__ __launch_bounds__(256) void gemm_tf32(
    const float* __restrict__ A, const float* __restrict__ W,
    const float* __restrict__ bias, float* __restrict__ C,
    int M, int N, int K)
{
    extern __shared__ float sm[];
    float* AsF = sm;
    float* BsF = sm + 2 * 128 * TPAD;

    int tid = threadIdx.x;
    int m0 = blockIdx.y << 7, n0 = blockIdx.x << 7;
    int lane = tid & 31, warp = tid >> 5;
    int mbase = (warp & 1) * 64;
    int nbase = (warp >> 1) * 32;
    int r = lane >> 2, cq = lane & 3;

    uint32_t aBase = (uint32_t)__cvta_generic_to_shared(AsF);
    uint32_t bBase = (uint32_t)__cvta_generic_to_shared(BsF);

    // ldmatrix per-lane tile-row/col selectors
    int arow = (lane & 7) + (((lane >> 3) & 1) << 3);   // row within 16-row A tile
    int acol = (lane >> 4) << 2;                        // 0 or 4
    int brow = (lane & 7) + ((lane >> 4) << 3);         // row within 16-row B group
    int bcol = ((lane >> 3) & 1) << 2;                  // 0 or 4

    float acc[4][4][4];
    #pragma unroll
    for (int mt = 0; mt < 4; mt++)
        #pragma unroll
        for (int nt = 0; nt < 4; nt++)
            #pragma unroll
            for (int i = 0; i < 4; i++) acc[mt][nt][i] = 0.f;

    auto issue_stage = [&](int s, int k0) {
        uint32_t so = (uint32_t)(s * 128 * TPAD) * 4u;
        #pragma unroll
        for (int j = 0; j < 4; j++) {
            int i = tid + (j << 8);
            int row = i >> 3, c4 = (i & 7) << 2;
            cpasync16(aBase + so + (uint32_t)(row * TPAD + c4) * 4u,
                      &A[(size_t)(m0 + row) * K + k0 + c4], 16u);
        }
        #pragma unroll
        for (int j = 0; j < 4; j++) {
            int i = tid + (j << 8);
            int row = i >> 3, c4 = (i & 7) << 2;
            int nrow = n0 + row;
            const float* gp = &W[(size_t)(nrow < N ? nrow : 0) * K + k0 + c4];
            cpasync16(bBase + so + (uint32_t)(row * TPAD + c4) * 4u,
                      gp, nrow < N ? 16u : 0u);
        }
    };

    int nk = K >> 5;
    issue_stage(0, 0);
    asm volatile("cp.async.commit_group;\n");

    for (int kt = 0; kt < nk; kt++) {
        int cur = kt & 1;
        if (kt + 1 < nk) {
            issue_stage(cur ^ 1, (kt + 1) << 5);
            asm volatile("cp.async.commit_group;\n");
            asm volatile("cp.async.wait_group 1;\n");
        } else {
            asm volatile("cp.async.wait_group 0;\n");
        }
        __syncthreads();

        uint32_t aS = aBase + (uint32_t)(cur * 128 * TPAD) * 4u;
        uint32_t bS = bBase + (uint32_t)(cur * 128 * TPAD) * 4u;
        #pragma unroll
        for (int ks = 0; ks < 32; ks += 8) {
            uint32_t a[4][4], b[4][2];
            #pragma unroll
            for (int mt = 0; mt < 4; mt++) {
                uint32_t addr = aS + (uint32_t)((mbase + mt * 16 + arow) * TPAD + ks + acol) * 4u;
                ldsm4(a[mt][0], a[mt][1], a[mt][2], a[mt][3], addr);
            }
            #pragma unroll
            for (int p = 0; p < 2; p++) {
                uint32_t addr = bS + (uint32_t)((nbase + p * 16 + brow) * TPAD + ks + bcol) * 4u;
                ldsm4(b[2*p][0], b[2*p][1], b[2*p+1][0], b[2*p+1][1], addr);
            }
            #pragma unroll
            for (int mt = 0; mt < 4; mt++)
                #pragma unroll
                for (int nt = 0; nt < 4; nt++)
                    mma_tf32(acc[mt][nt], a[mt][0], a[mt][1], a[mt][2], a[mt][3],
                             b[nt][0], b[nt][1]);
        }
        __syncthreads();
    }

    #pragma unroll
    for (int mt = 0; mt < 4; mt++) {
        #pragma unroll
        for (int nt = 0; nt < 4; nt++) {
            int row = m0 + mbase + mt * 16 + r;
            int col = n0 + nbase + nt * 8 + 2 * cq;
            if (col < N) {
                float b0 = __ldg(&bias[col]), b1 = __ldg(&bias[col + 1]);
                C[(size_t)row * N + col]           = acc[mt][nt][0] + b0;
                C[(size_t)row * N + col + 1]       = acc[mt][nt][1] + b1;
                C[(size_t)(row + 8) * N + col]     = acc[mt][nt][2] + b0;
                C[(size_t)(row + 8) * N + col + 1] = acc[mt][nt][3] + b1;
            }
        }
    }
}

// ---------------- RMS norm (output rounded to tf32) ----------------
__global__ __launch_bounds__(256) void rms_kernel(
    const float* __restrict__ in, int inStride, int W,
    const float* __restrict__ g, float* __restrict__ out)
{
    int row = blockIdx.x;
    const float* x = in + (size_t)row * inStride;
    float s = 0.f;
    for (int i = threadIdx.x; i < W; i += 256) { float v = x[i]; s += v * v; }
    #pragma unroll
    for (int off = 16; off; off >>= 1) s += __shfl_xor_sync(0xffffffffu, s, off);
    __shared__ float red[8];
    int w = threadIdx.x >> 5;
    if ((threadIdx.x & 31) == 0) red[w] = s;
    __syncthreads();
    if (w == 0) {
        float v = (threadIdx.x < 8) ? red[threadIdx.x] : 0.f;
        #pragma unroll
        for (int off = 4; off; off >>= 1) v += __shfl_xor_sync(0xffffffffu, v, off);
        if (threadIdx.x == 0) red[0] = v;
    }
    __syncthreads();
    float inv = rsqrtf(red[0] / (float)W + 1e-6f);
    for (int i = threadIdx.x; i < W; i += 256)
        out[(size_t)row * W + i] = f2tf_f(x[i] * inv * g[i]);
}

// ---------------- RoPE q ----------------
__global__ __launch_bounds__(256) void rope_q_kernel(
    float* __restrict__ q, const float* __restrict__ bf)
{
    int idx = blockIdx.x * 256 + threadIdx.x;
    int j = idx & 31;
    int h = (idx >> 5) & 15;
    int s = (idx >> 9) & 1023;
    int b = idx >> 19;
    float ang = bf[s * 64 + j];
    float c = cosf(ang), sn = sinf(ang);
    float* p = q + ((size_t)((b * NS + s) * NH + h)) * NQKH + NNOPE;
    float x1 = p[j], x2 = p[j + 32];
    p[j]      = x1 * c - x2 * sn;
    p[j + 32] = x2 * c + x1 * sn;
}

// ---------------- RoPE k ----------------
__global__ __launch_bounds__(256) void rope_k_kernel(
    const float* __restrict__ kv, const float* __restrict__ bf,
    float* __restrict__ krot)
{
    int idx = blockIdx.x * 256 + threadIdx.x;
    int j = idx & 31;
    int row = idx >> 5;
    int s = row & 1023;
    float ang = bf[s * 64 + j];
    float c = cosf(ang), sn = sinf(ang);
    float x1 = kv[(size_t)row * (NKVL + NROPE) + NKVL + j];
    float x2 = kv[(size_t)row * (NKVL + NROPE) + NKVL + 32 + j];
    krot[(size_t)row * 64 + j]      = x1 * c - x2 * sn;
    krot[(size_t)row * 64 + 32 + j] = x2 * c + x1 * sn;
}

// ---------------- tensor-core flash attention (3xTF32 = fp32 accuracy) ----------------
#define QPAD 196
#define KPAD 196
#define VPAD 136
#define PPAD 68
#define ATTN_SMEM ((128*QPAD + 64*KPAD + 64*VPAD + 128*PPAD) * 4)

__global__ __launch_bounds__(256) void attn_tc_kernel(
    const float* __restrict__ q, const float* __restrict__ kvu,
    const float* __restrict__ krot, const int* __restrict__ startp,
    float* __restrict__ out)
{
    extern __shared__ float sm[];
    float* Qs = sm;
    float* Ks = Qs + 128 * QPAD;
    float* Vs = Ks + 64 * KPAD;
    float* Ps = Vs + 64 * VPAD;

    int qt = blockIdx.x, h = blockIdx.y, b = blockIdx.z;
    int q0 = qt << 7;
    int start = *startp;
    int tid = threadIdx.x, lane = tid & 31, warp = tid >> 5;
    int r = lane >> 2, cq = lane & 3;
    int mbase = warp << 4;
    const float scale = rsqrtf((float)NQKH);

    for (int p = tid * 4; p < 128 * 192; p += 1024) {
        int row = p / 192, d = p % 192;
        float4 v = *(const float4*)&q[((size_t)((b * NS + q0 + row) * NH + h)) * NQKH + d];
        v.x *= scale; v.y *= scale; v.z *= scale; v.w *= scale;
        *(float4*)&Qs[row * QPAD + d] = v;
    }

    float m_i[2] = {-1e30f, -1e30f}, l_i[2] = {0.f, 0.f};
    float acc[16][4];
    #pragma unroll
    for (int nt = 0; nt < 16; nt++)
        #pragma unroll
        for (int i = 0; i < 4; i++) acc[nt][i] = 0.f;

    int kmax = q0 + 128 + start; if (kmax > NS) kmax = NS;
    int nch = (kmax + 63) >> 6;
    int qrow0 = q0 + mbase + r;

    for (int c = 0; c < nch; c++) {
        int k0 = c << 6;
        __syncthreads();
        for (int p = tid * 4; p < 64 * 192; p += 1024) {
            int row = p / 192, d = p % 192;
            int grow = b * NS + k0 + row;
            float4 v;
            if (d < 128) v = *(const float4*)&kvu[((size_t)grow * NH + h) * 256 + d];
            else         v = *(const float4*)&krot[(size_t)grow * 64 + (d - 128)];
            *(float4*)&Ks[row * KPAD + d] = v;
        }
        for (int p = tid * 4; p < 64 * 128; p += 1024) {
            int row = p >> 7, d = p & 127;
            float4 v = *(const float4*)&kvu[((size_t)(b * NS + k0 + row) * NH + h) * 256 + 128 + d];
            *(float4*)&Vs[row * VPAD + d] = v;
        }
        __syncthreads();

        float s_acc[8][4];
        #pragma unroll
        for (int nt = 0; nt < 8; nt++)
            #pragma unroll
            for (int i = 0; i < 4; i++) s_acc[nt][i] = 0.f;

        #pragma unroll 4
        for (int kt = 0; kt < 24; kt++) {
            int ko = kt << 3;
            uint32_t ah[4], al[4];
            split_tf(Qs[(mbase + r) * QPAD + ko + cq],         ah[0], al[0]);
            split_tf(Qs[(mbase + r + 8) * QPAD + ko + cq],     ah[1], al[1]);
            split_tf(Qs[(mbase + r) * QPAD + ko + cq + 4],     ah[2], al[2]);
            split_tf(Qs[(mbase + r + 8) * QPAD + ko + cq + 4], ah[3], al[3]);
            #pragma unroll
            for (int nt = 0; nt < 8; nt++) {
                uint32_t bh[2], bl[2];
                split_tf(Ks[(nt * 8 + r) * KPAD + ko + cq],     bh[0], bl[0]);
                split_tf(Ks[(nt * 8 + r) * KPAD + ko + cq + 4], bh[1], bl[1]);
                mma_tf32(s_acc[nt], ah[0], ah[1], ah[2], ah[3], bh[0], bh[1]);
                mma_tf32(s_acc[nt], ah[0], ah[1], ah[2], ah[3], bl[0], bl[1]);
                mma_tf32(s_acc[nt], al[0], al[1], al[2], al[3], bh[0], bh[1]);
            }
        }

        #pragma unroll
        for (int nt = 0; nt < 8; nt++) {
            int col = k0 + nt * 8 + 2 * cq;
            if (col     > qrow0 + start)     s_acc[nt][0] = -1e30f;
            if (col + 1 > qrow0 + start)     s_acc[nt][1] = -1e30f;
            if (col     > qrow0 + 8 + start) s_acc[nt][2] = -1e30f;
            if (col + 1 > qrow0 + 8 + start) s_acc[nt][3] = -1e30f;
        }
        float mx0 = -1e30f, mx1 = -1e30f;
        #pragma unroll
        for (int nt = 0; nt < 8; nt++) {
            mx0 = fmaxf(mx0, fmaxf(s_acc[nt][0], s_acc[nt][1]));
            mx1 = fmaxf(mx1, fmaxf(s_acc[nt][2], s_acc[nt][3]));
        }
        mx0 = fmaxf(mx0, __shfl_xor_sync(0xffffffffu, mx0, 1));
        mx0 = fmaxf(mx0, __shfl_xor_sync(0xffffffffu, mx0, 2));
        mx1 = fmaxf(mx1, __shfl_xor_sync(0xffffffffu, mx1, 1));
        mx1 = fmaxf(mx1, __shfl_xor_sync(0xffffffffu, mx1, 2));

        float mn0 = fmaxf(m_i[0], mx0), mn1 = fmaxf(m_i[1], mx1);
        float fac0 = __expf(m_i[0] - mn0), fac1 = __expf(m_i[1] - mn1);
        float sum0 = 0.f, sum1 = 0.f;
        #pragma unroll
        for (int nt = 0; nt < 8; nt++) {
            s_acc[nt][0] = __expf(s_acc[nt][0] - mn0);
            s_acc[nt][1] = __expf(s_acc[nt][1] - mn0);
            s_acc[nt][2] = __expf(s_acc[nt][2] - mn1);
            s_acc[nt][3] = __expf(s_acc[nt][3] - mn1);
            sum0 += s_acc[nt][0] + s_acc[nt][1];
            sum1 += s_acc[nt][2] + s_acc[nt][3];
        }
        sum0 += __shfl_xor_sync(0xffffffffu, sum0, 1);
        sum0 += __shfl_xor_sync(0xffffffffu, sum0, 2);
        sum1 += __shfl_xor_sync(0xffffffffu, sum1, 1);
        sum1 += __shfl_xor_sync(0xffffffffu, sum1, 2);
        l_i[0] = l_i[0] * fac0 + sum0;
        l_i[1] = l_i[1] * fac1 + sum1;
        m_i[0] = mn0; m_i[1] = mn1;
        #pragma unroll
        for (int nt = 0; nt < 16; nt++) {
            acc[nt][0] *= fac0; acc[nt][1] *= fac0;
            acc[nt][2] *= fac1; acc[nt][3] *= fac1;
        }
        #pragma unroll
        for (int nt = 0; nt < 8; nt++) {
            int colo = nt * 8 + 2 * cq;
            Ps[(mbase + r) * PPAD + colo]         = s_acc[nt][0];
            Ps[(mbase + r) * PPAD + colo + 1]     = s_acc[nt][1];
            Ps[(mbase + r + 8) * PPAD + colo]     = s_acc[nt][2];
            Ps[(mbase + r + 8) * PPAD + colo + 1] = s_acc[nt][3];
        }
        __syncwarp();

        #pragma unroll
        for (int kt = 0; kt < 8; kt++) {
            int ko = kt << 3;
            uint32_t ah[4], al[4];
            split_tf(Ps[(mbase + r) * PPAD + ko + cq],         ah[0], al[0]);
            split_tf(Ps[(mbase + r + 8) * PPAD + ko + cq],     ah[1], al[1]);
            split_tf(Ps[(mbase + r) * PPAD + ko + cq + 4],     ah[2], al[2]);
            split_tf(Ps[(mbase + r + 8) * PPAD + ko + cq + 4], ah[3], al[3]);
            #pragma unroll
            for (int nt = 0; nt < 16; nt++) {
                uint32_t bh[2], bl[2];
                split_tf(Vs[(ko + cq) * VPAD + nt * 8 + r],     bh[0], bl[0]);
                split_tf(Vs[(ko + cq + 4) * VPAD + nt * 8 + r], bh[1], bl[1]);
                mma_tf32(acc[nt], ah[0], ah[1], ah[2], ah[3], bh[0], bh[1]);
                mma_tf32(acc[nt], ah[0], ah[1], ah[2], ah[3], bl[0], bl[1]);
                mma_tf32(acc[nt], al[0], al[1], al[2], al[3], bh[0], bh[1]);
            }
        }
    }

    float inv0 = 1.f / l_i[0], inv1 = 1.f / l_i[1];
    size_t o0 = ((size_t)((b * NS + q0 + mbase + r) * NH + h)) * NVH;
    size_t o1 = ((size_t)((b * NS + q0 + mbase + r + 8) * NH + h)) * NVH;
    #pragma unroll
    for (int nt = 0; nt < 16; nt++) {
        int col = nt * 8 + 2 * cq;
        *(float2*)&out[o0 + col] = make_float2(f2tf_f(acc[nt][0] * inv0), f2tf_f(acc[nt][1] * inv0));
        *(float2*)&out[o1 + col] = make_float2(f2tf_f(acc[nt][2] * inv1), f2tf_f(acc[nt][3] * inv1));
    }
}

// ---------------- launch ----------------
extern "C" void kernel_launch(void* const* d_in, const int* in_sizes, int n_in,
                              void* d_out, int out_size)
{
    const float* X    = (const float*)d_in[0];
    const float* bf   = (const float*)d_in[1];
    const float* Wqd  = (const float*)d_in[2];
    const float* bqd  = (const float*)d_in[3];
    const float* gq   = (const float*)d_in[4];
    const float* Wqu  = (const float*)d_in[5];
    const float* bqu  = (const float*)d_in[6];
    const float* Wkv  = (const float*)d_in[7];
    const float* bkv  = (const float*)d_in[8];
    const float* gkv  = (const float*)d_in[9];
    const float* Wkvu = (const float*)d_in[10];
    const float* bkvu = (const float*)d_in[11];
    const float* Wo   = (const float*)d_in[12];
    const float* bo   = (const float*)d_in[13];
    const int*   stp  = (const int*)d_in[14];
    float* out = (float*)d_out;

    float *qd, *qdn, *q, *kv, *kvn, *kvu, *krot, *att;
    float *xtf, *wqd, *wqu, *wkv, *wkvu, *wo;
    cudaGetSymbolAddress((void**)&qd,   g_qd);
    cudaGetSymbolAddress((void**)&qdn,  g_qdn);
    cudaGetSymbolAddress((void**)&q,    g_q);
    cudaGetSymbolAddress((void**)&kv,   g_kv);
    cudaGetSymbolAddress((void**)&kvn,  g_kvn);
    cudaGetSymbolAddress((void**)&kvu,  g_kvu);
    cudaGetSymbolAddress((void**)&krot, g_krot);
    cudaGetSymbolAddress((void**)&att,  g_att);
    cudaGetSymbolAddress((void**)&xtf,  g_xtf);
    cudaGetSymbolAddress((void**)&wqd,  g_wqd);
    cudaGetSymbolAddress((void**)&wqu,  g_wqu);
    cudaGetSymbolAddress((void**)&wkv,  g_wkv);
    cudaGetSymbolAddress((void**)&wkvu, g_wkvu);
    cudaGetSymbolAddress((void**)&wo,   g_wo);

    cudaFuncSetAttribute(gemm_tf32, cudaFuncAttributeMaxDynamicSharedMemorySize, GSMEM);
    cudaFuncSetAttribute(attn_tc_kernel, cudaFuncAttributeMaxDynamicSharedMemorySize, ATTN_SMEM);

    // pre-round inputs/weights to tf32
    tf32_round_kernel<<<(NM*ND/4 + 255)/256, 256>>>(X, xtf, NM*ND/4);
    tf32_round_kernel<<<(NQL*ND/4 + 255)/256, 256>>>(Wqd, wqd, NQL*ND/4);
    tf32_round_kernel<<<(NH*NQKH*NQL/4 + 255)/256, 256>>>(Wqu, wqu, NH*NQKH*NQL/4);
    tf32_round_kernel<<<((NKVL+NROPE)*ND/4 + 255)/256, 256>>>(Wkv, wkv, (NKVL+NROPE)*ND/4);
    tf32_round_kernel<<<(NH*(NNOPE+NVH)*NKVL/4 + 255)/256, 256>>>(Wkvu, wkvu, NH*(NNOPE+NVH)*NKVL/4);
    tf32_round_kernel<<<(ND*NH*NVH/4 + 255)/256, 256>>>(Wo, wo, ND*NH*NVH/4);

    // q path
    gemm_tf32<<<dim3(NQL/128, NM/128), 256, GSMEM>>>(xtf, wqd, bqd, qd, NM, NQL, ND);
    rms_kernel<<<NM, 256>>>(qd, NQL, NQL, gq, qdn);
    gemm_tf32<<<dim3((NH*NQKH)/128, NM/128), 256, GSMEM>>>(qdn, wqu, bqu, q, NM, NH*NQKH, NQL);
    rope_q_kernel<<<(NM*NH*32)/256, 256>>>(q, bf);

    // kv path
    gemm_tf32<<<dim3((NKVL+NROPE+127)/128, NM/128), 256, GSMEM>>>(xtf, wkv, bkv, kv, NM, NKVL+NROPE, ND);
    rms_kernel<<<NM, 256>>>(kv, NKVL+NROPE, NKVL, gkv, kvn);
    gemm_tf32<<<dim3((NH*(NNOPE+NVH))/128, NM/128), 256, GSMEM>>>(kvn, wkvu, bkvu, kvu, NM, NH*(NNOPE+NVH), NKVL);
    rope_k_kernel<<<(NM*32)/256, 256>>>(kv, bf, krot);

    // attention (tensor core)
    attn_tc_kernel<<<dim3(NS/128, NH, NB), 256, ATTN_SMEM>>>(q, kvu, krot, stp, att);

    // output projection -> d_out
    gemm_tf32<<<dim3(ND/128, NM/128), 256, GSMEM>>>(att, wo, bo, out, NM, ND, ND);
}

// round 13
// speedup vs baseline: 1.0848x; 1.0848x over previous
#include <cuda_runtime.h>
#include <cstdint>

// ---------------- problem constants ----------------
#define NB 4
#define NS 1024
#define ND 2048
#define NH 16
#define NQL 1536
#define NKVL 512
#define NNOPE 128
#define NROPE 64
#define NVH 128
#define NQKH 192
#define NM (NB*NS)          // 4096 token rows

// ---------------- scratch ----------------
__device__ float g_qd  [NM*NQL];
__device__ float g_qdn [NM*NQL];
__device__ float g_q   [NM*NH*NQKH];
__device__ float g_kv  [NM*(NKVL+NROPE)];
__device__ float g_kvn [NM*NKVL];
__device__ float g_kvu [NM*NH*(NNOPE+NVH)];
__device__ float g_krot[NM*NROPE];
__device__ float g_att [NM*NH*NVH];
// tf32-rounded copies (inputs to GEMMs)
__device__ float g_xtf [NM*ND];
__device__ float g_wqd [NQL*ND];
__device__ float g_wqu [NH*NQKH*NQL];
__device__ float g_wkv [(NKVL+NROPE)*ND];
__device__ float g_wkvu[NH*(NNOPE+NVH)*NKVL];
__device__ float g_wo  [ND*NH*NVH];

// ---------------- helpers ----------------
__device__ __forceinline__ uint32_t f2tf(float x) {
    uint32_t y;
    asm("cvt.rna.tf32.f32 %0, %1;" : "=r"(y) : "f"(x));
    return y;
}
__device__ __forceinline__ float f2tf_f(float x) { return __uint_as_float(f2tf(x)); }
__device__ __forceinline__ void split_tf(float x, uint32_t& hi, uint32_t& lo) {
    hi = f2tf(x);
    lo = f2tf(x - __uint_as_float(hi));
}
__device__ __forceinline__ void mma_tf32(float* c,
    uint32_t a0, uint32_t a1, uint32_t a2, uint32_t a3,
    uint32_t b0, uint32_t b1)
{
    asm volatile(
        "mma.sync.aligned.m16n8k8.row.col.f32.tf32.tf32.f32 "
        "{%0,%1,%2,%3}, {%4,%5,%6,%7}, {%8,%9}, {%0,%1,%2,%3};\n"
        : "+f"(c[0]), "+f"(c[1]), "+f"(c[2]), "+f"(c[3])
        : "r"(a0), "r"(a1), "r"(a2), "r"(a3), "r"(b0), "r"(b1));
}
__device__ __forceinline__ void cpasync16(uint32_t saddr, const void* g, uint32_t sz) {
    asm volatile("cp.async.cg.shared.global [%0], [%1], 16, %2;\n"
                 :: "r"(saddr), "l"(g), "r"(sz));
}

// ---------------- tf32 pre-round ----------------
__global__ __launch_bounds__(256) void tf32_round_kernel(
    const float* __restrict__ in, float* __restrict__ out, int n4)
{
    int i = blockIdx.x * 256 + threadIdx.x;
    if (i < n4) {
        float4 v = ((const float4*)in)[i];
        v.x = f2tf_f(v.x); v.y = f2tf_f(v.y); v.z = f2tf_f(v.z); v.w = f2tf_f(v.w);
        ((float4*)out)[i] = v;
    }
}

// ---------------- shared GEMM body (R9 config: cp.async 2-stage, scalar LDS frags) ----------------
#define TPAD 36
#define GSMEM (2 * 2 * 128 * TPAD * 4)   // 72 KB -> 2 CTAs/SM

__device__ __forceinline__ void gemm_body(
    const float* __restrict__ A, const float* __restrict__ W,
    const float* __restrict__ bias, float* __restrict__ C,
    int N, int K, int m0, int n0, float* sm)
{
    float* AsF = sm;
    float* BsF = sm + 2 * 128 * TPAD;

    int tid = threadIdx.x;
    int lane = tid & 31, warp = tid >> 5;
    int mbase = (warp & 1) * 64;
    int nbase = (warp >> 1) * 32;
    int r = lane >> 2, cq = lane & 3;

    uint32_t aBase = (uint32_t)__cvta_generic_to_shared(AsF);
    uint32_t bBase = (uint32_t)__cvta_generic_to_shared(BsF);

    float acc[4][4][4];
    #pragma unroll
    for (int mt = 0; mt < 4; mt++)
        #pragma unroll
        for (int nt = 0; nt < 4; nt++)
            #pragma unroll
            for (int i = 0; i < 4; i++) acc[mt][nt][i] = 0.f;

    auto issue_stage = [&](int s, int k0) {
        uint32_t so = (uint32_t)(s * 128 * TPAD) * 4u;
        #pragma unroll
        for (int j = 0; j < 4; j++) {
            int i = tid + (j << 8);
            int row = i >> 3, c4 = (i & 7) << 2;
            cpasync16(aBase + so + (uint32_t)(row * TPAD + c4) * 4u,
                      &A[(size_t)(m0 + row) * K + k0 + c4], 16u);
        }
        #pragma unroll
        for (int j = 0; j < 4; j++) {
            int i = tid + (j << 8);
            int row = i >> 3, c4 = (i & 7) << 2;
            int nrow = n0 + row;
            const float* gp = &W[(size_t)(nrow < N ? nrow : 0) * K + k0 + c4];
            cpasync16(bBase + so + (uint32_t)(row * TPAD + c4) * 4u,
                      gp, nrow < N ? 16u : 0u);
        }
    };

    int nk = K >> 5;
    issue_stage(0, 0);
    asm volatile("cp.async.commit_group;\n");

    for (int kt = 0; kt < nk; kt++) {
        int cur = kt & 1;
        if (kt + 1 < nk) {
            issue_stage(cur ^ 1, (kt + 1) << 5);
            asm volatile("cp.async.commit_group;\n");
            asm volatile("cp.async.wait_group 1;\n");
        } else {
            asm volatile("cp.async.wait_group 0;\n");
        }
        __syncthreads();

        const float* Ac = AsF + cur * 128 * TPAD;
        const float* Bc = BsF + cur * 128 * TPAD;
        #pragma unroll
        for (int ks = 0; ks < 32; ks += 8) {
            uint32_t a[4][4], b[4][2];
            #pragma unroll
            for (int mt = 0; mt < 4; mt++) {
                int row = mbase + mt * 16 + r;
                a[mt][0] = __float_as_uint(Ac[row * TPAD + ks + cq]);
                a[mt][1] = __float_as_uint(Ac[(row + 8) * TPAD + ks + cq]);
                a[mt][2] = __float_as_uint(Ac[row * TPAD + ks + cq + 4]);
                a[mt][3] = __float_as_uint(Ac[(row + 8) * TPAD + ks + cq + 4]);
            }
            #pragma unroll
            for (int nt = 0; nt < 4; nt++) {
                int ncol = nbase + nt * 8 + r;
                b[nt][0] = __float_as_uint(Bc[ncol * TPAD + ks + cq]);
                b[nt][1] = __float_as_uint(Bc[ncol * TPAD + ks + cq + 4]);
            }
            #pragma unroll
            for (int mt = 0; mt < 4; mt++)
                #pragma unroll
                for (int nt = 0; nt < 4; nt++)
                    mma_tf32(acc[mt][nt], a[mt][0], a[mt][1], a[mt][2], a[mt][3],
                             b[nt][0], b[nt][1]);
        }
        __syncthreads();
    }

    #pragma unroll
    for (int mt = 0; mt < 4; mt++) {
        #pragma unroll
        for (int nt = 0; nt < 4; nt++) {
            int row = m0 + mbase + mt * 16 + r;
            int col = n0 + nbase + nt * 8 + 2 * cq;
            if (col < N) {
                float b0 = __ldg(&bias[col]), b1 = __ldg(&bias[col + 1]);
                C[(size_t)row * N + col]           = acc[mt][nt][0] + b0;
                C[(size_t)row * N + col + 1]       = acc[mt][nt][1] + b1;
                C[(size_t)(row + 8) * N + col]     = acc[mt][nt][2] + b0;
                C[(size_t)(row + 8) * N + col + 1] = acc[mt][nt][3] + b1;
            }
        }
    }
}

// plain single GEMM
__global__ __launch_bounds__(256) void gemm_tf32(
    const float* __restrict__ A, const float* __restrict__ W,
    const float* __restrict__ bias, float* __restrict__ C,
    int M, int N, int K)
{
    extern __shared__ float sm[];
    gemm_body(A, W, bias, C, N, K, blockIdx.y << 7, blockIdx.x << 7, sm);
}

// dual-N GEMM: two outputs sharing the SAME A and SAME K (down-projection pair).
// bx < nx1 -> side 1, else side 2. Uniform K so no mixed-depth wave drain.
__global__ __launch_bounds__(256) void gemm_dualN(
    const float* __restrict__ A,
    const float* __restrict__ W1, const float* __restrict__ b1,
    float* __restrict__ C1, int N1, int nx1,
    const float* __restrict__ W2, const float* __restrict__ b2,
    float* __restrict__ C2, int N2, int K)
{
    extern __shared__ float sm[];
    int bx = blockIdx.x;
    if (bx < nx1)
        gemm_body(A, W1, b1, C1, N1, K, blockIdx.y << 7, bx << 7, sm);
    else
        gemm_body(A, W2, b2, C2, N2, K, blockIdx.y << 7, (bx - nx1) << 7, sm);
}

// ---------------- RMS norm (output rounded to tf32) ----------------
__global__ __launch_bounds__(256) void rms_kernel(
    const float* __restrict__ in, int inStride, int W,
    const float* __restrict__ g, float* __restrict__ out)
{
    int row = blockIdx.x;
    const float* x = in + (size_t)row * inStride;
    float s = 0.f;
    for (int i = threadIdx.x; i < W; i += 256) { float v = x[i]; s += v * v; }
    #pragma unroll
    for (int off = 16; off; off >>= 1) s += __shfl_xor_sync(0xffffffffu, s, off);
    __shared__ float red[8];
    int w = threadIdx.x >> 5;
    if ((threadIdx.x & 31) == 0) red[w] = s;
    __syncthreads();
    if (w == 0) {
        float v = (threadIdx.x < 8) ? red[threadIdx.x] : 0.f;
        #pragma unroll
        for (int off = 4; off; off >>= 1) v += __shfl_xor_sync(0xffffffffu, v, off);
        if (threadIdx.x == 0) red[0] = v;
    }
    __syncthreads();
    float inv = rsqrtf(red[0] / (float)W + 1e-6f);
    for (int i = threadIdx.x; i < W; i += 256)
        out[(size_t)row * W + i] = f2tf_f(x[i] * inv * g[i]);
}

// ---------------- RoPE q ----------------
__global__ __launch_bounds__(256) void rope_q_kernel(
    float* __restrict__ q, const float* __restrict__ bf)
{
    int idx = blockIdx.x * 256 + threadIdx.x;
    int j = idx & 31;
    int h = (idx >> 5) & 15;
    int s = (idx >> 9) & 1023;
    int b = idx >> 19;
    float ang = bf[s * 64 + j];
    float c = cosf(ang), sn = sinf(ang);
    float* p = q + ((size_t)((b * NS + s) * NH + h)) * NQKH + NNOPE;
    float x1 = p[j], x2 = p[j + 32];
    p[j]      = x1 * c - x2 * sn;
    p[j + 32] = x2 * c + x1 * sn;
}

// ---------------- RoPE k ----------------
__global__ __launch_bounds__(256) void rope_k_kernel(
    const float* __restrict__ kv, const float* __restrict__ bf,
    float* __restrict__ krot)
{
    int idx = blockIdx.x * 256 + threadIdx.x;
    int j = idx & 31;
    int row = idx >> 5;
    int s = row & 1023;
    float ang = bf[s * 64 + j];
    float c = cosf(ang), sn = sinf(ang);
    float x1 = kv[(size_t)row * (NKVL + NROPE) + NKVL + j];
    float x2 = kv[(size_t)row * (NKVL + NROPE) + NKVL + 32 + j];
    krot[(size_t)row * 64 + j]      = x1 * c - x2 * sn;
    krot[(size_t)row * 64 + 32 + j] = x2 * c + x1 * sn;
}

// ---------------- tensor-core flash attention (3xTF32 = fp32 accuracy) ----------------
#define QPAD 196
#define KPAD 196
#define VPAD 136
#define PPAD 68
#define ATTN_SMEM ((128*QPAD + 64*KPAD + 64*VPAD + 128*PPAD) * 4)

__global__ __launch_bounds__(256) void attn_tc_kernel(
    const float* __restrict__ q, const float* __restrict__ kvu,
    const float* __restrict__ krot, const int* __restrict__ startp,
    float* __restrict__ out)
{
    extern __shared__ float sm[];
    float* Qs = sm;
    float* Ks = Qs + 128 * QPAD;
    float* Vs = Ks + 64 * KPAD;
    float* Ps = Vs + 64 * VPAD;

    int qt = blockIdx.x, h = blockIdx.y, b = blockIdx.z;
    int q0 = qt << 7;
    int start = *startp;
    int tid = threadIdx.x, lane = tid & 31, warp = tid >> 5;
    int r = lane >> 2, cq = lane & 3;
    int mbase = warp << 4;
    const float scale = rsqrtf((float)NQKH);

    for (int p = tid * 4; p < 128 * 192; p += 1024) {
        int row = p / 192, d = p % 192;
        float4 v = *(const float4*)&q[((size_t)((b * NS + q0 + row) * NH + h)) * NQKH + d];
        v.x *= scale; v.y *= scale; v.z *= scale; v.w *= scale;
        *(float4*)&Qs[row * QPAD + d] = v;
    }

    float m_i[2] = {-1e30f, -1e30f}, l_i[2] = {0.f, 0.f};
    float acc[16][4];
    #pragma unroll
    for (int nt = 0; nt < 16; nt++)
        #pragma unroll
        for (int i = 0; i < 4; i++) acc[nt][i] = 0.f;

    int kmax = q0 + 128 + start; if (kmax > NS) kmax = NS;
    int nch = (kmax + 63) >> 6;
    int qrow0 = q0 + mbase + r;

    for (int c = 0; c < nch; c++) {
        int k0 = c << 6;
        __syncthreads();
        for (int p = tid * 4; p < 64 * 192; p += 1024) {
            int row = p / 192, d = p % 192;
            int grow = b * NS + k0 + row;
            float4 v;
            if (d < 128) v = *(const float4*)&kvu[((size_t)grow * NH + h) * 256 + d];
            else         v = *(const float4*)&krot[(size_t)grow * 64 + (d - 128)];
            *(float4*)&Ks[row * KPAD + d] = v;
        }
        for (int p = tid * 4; p < 64 * 128; p += 1024) {
            int row = p >> 7, d = p & 127;
            float4 v = *(const float4*)&kvu[((size_t)(b * NS + k0 + row) * NH + h) * 256 + 128 + d];
            *(float4*)&Vs[row * VPAD + d] = v;
        }
        __syncthreads();

        float s_acc[8][4];
        #pragma unroll
        for (int nt = 0; nt < 8; nt++)
            #pragma unroll
            for (int i = 0; i < 4; i++) s_acc[nt][i] = 0.f;

        #pragma unroll 4
        for (int kt = 0; kt < 24; kt++) {
            int ko = kt << 3;
            uint32_t ah[4], al[4];
            split_tf(Qs[(mbase + r) * QPAD + ko + cq],         ah[0], al[0]);
            split_tf(Qs[(mbase + r + 8) * QPAD + ko + cq],     ah[1], al[1]);
            split_tf(Qs[(mbase + r) * QPAD + ko + cq + 4],     ah[2], al[2]);
            split_tf(Qs[(mbase + r + 8) * QPAD + ko + cq + 4], ah[3], al[3]);
            #pragma unroll
            for (int nt = 0; nt < 8; nt++) {
                uint32_t bh[2], bl[2];
                split_tf(Ks[(nt * 8 + r) * KPAD + ko + cq],     bh[0], bl[0]);
                split_tf(Ks[(nt * 8 + r) * KPAD + ko + cq + 4], bh[1], bl[1]);
                mma_tf32(s_acc[nt], ah[0], ah[1], ah[2], ah[3], bh[0], bh[1]);
                mma_tf32(s_acc[nt], ah[0], ah[1], ah[2], ah[3], bl[0], bl[1]);
                mma_tf32(s_acc[nt], al[0], al[1], al[2], al[3], bh[0], bh[1]);
            }
        }

        #pragma unroll
        for (int nt = 0; nt < 8; nt++) {
            int col = k0 + nt * 8 + 2 * cq;
            if (col     > qrow0 + start)     s_acc[nt][0] = -1e30f;
            if (col + 1 > qrow0 + start)     s_acc[nt][1] = -1e30f;
            if (col     > qrow0 + 8 + start) s_acc[nt][2] = -1e30f;
            if (col + 1 > qrow0 + 8 + start) s_acc[nt][3] = -1e30f;
        }
        float mx0 = -1e30f, mx1 = -1e30f;
        #pragma unroll
        for (int nt = 0; nt < 8; nt++) {
            mx0 = fmaxf(mx0, fmaxf(s_acc[nt][0], s_acc[nt][1]));
            mx1 = fmaxf(mx1, fmaxf(s_acc[nt][2], s_acc[nt][3]));
        }
        mx0 = fmaxf(mx0, __shfl_xor_sync(0xffffffffu, mx0, 1));
        mx0 = fmaxf(mx0, __shfl_xor_sync(0xffffffffu, mx0, 2));
        mx1 = fmaxf(mx1, __shfl_xor_sync(0xffffffffu, mx1, 1));
        mx1 = fmaxf(mx1, __shfl_xor_sync(0xffffffffu, mx1, 2));

        float mn0 = fmaxf(m_i[0], mx0), mn1 = fmaxf(m_i[1], mx1);
        float fac0 = __expf(m_i[0] - mn0), fac1 = __expf(m_i[1] - mn1);
        float sum0 = 0.f, sum1 = 0.f;
        #pragma unroll
        for (int nt = 0; nt < 8; nt++) {
            s_acc[nt][0] = __expf(s_acc[nt][0] - mn0);
            s_acc[nt][1] = __expf(s_acc[nt][1] - mn0);
            s_acc[nt][2] = __expf(s_acc[nt][2] - mn1);
            s_acc[nt][3] = __expf(s_acc[nt][3] - mn1);
            sum0 += s_acc[nt][0] + s_acc[nt][1];
            sum1 += s_acc[nt][2] + s_acc[nt][3];
        }
        sum0 += __shfl_xor_sync(0xffffffffu, sum0, 1);
        sum0 += __shfl_xor_sync(0xffffffffu, sum0, 2);
        sum1 += __shfl_xor_sync(0xffffffffu, sum1, 1);
        sum1 += __shfl_xor_sync(0xffffffffu, sum1, 2);
        l_i[0] = l_i[0] * fac0 + sum0;
        l_i[1] = l_i[1] * fac1 + sum1;
        m_i[0] = mn0; m_i[1] = mn1;
        #pragma unroll
        for (int nt = 0; nt < 16; nt++) {
            acc[nt][0] *= fac0; acc[nt][1] *= fac0;
            acc[nt][2] *= fac1; acc[nt][3] *= fac1;
        }
        #pragma unroll
        for (int nt = 0; nt < 8; nt++) {
            int colo = nt * 8 + 2 * cq;
            Ps[(mbase + r) * PPAD + colo]         = s_acc[nt][0];
            Ps[(mbase + r) * PPAD + colo + 1]     = s_acc[nt][1];
            Ps[(mbase + r + 8) * PPAD + colo]     = s_acc[nt][2];
            Ps[(mbase + r + 8) * PPAD + colo + 1] = s_acc[nt][3];
        }
        __syncwarp();

        #pragma unroll
        for (int kt = 0; kt < 8; kt++) {
            int ko = kt << 3;
            uint32_t ah[4], al[4];
            split_tf(Ps[(mbase + r) * PPAD + ko + cq],         ah[0], al[0]);
            split_tf(Ps[(mbase + r + 8) * PPAD + ko + cq],     ah[1], al[1]);
            split_tf(Ps[(mbase + r) * PPAD + ko + cq + 4],     ah[2], al[2]);
            split_tf(Ps[(mbase + r + 8) * PPAD + ko + cq + 4], ah[3], al[3]);
            #pragma unroll
            for (int nt = 0; nt < 16; nt++) {
                uint32_t bh[2], bl[2];
                split_tf(Vs[(ko + cq) * VPAD + nt * 8 + r],     bh[0], bl[0]);
                split_tf(Vs[(ko + cq + 4) * VPAD + nt * 8 + r], bh[1], bl[1]);
                mma_tf32(acc[nt], ah[0], ah[1], ah[2], ah[3], bh[0], bh[1]);
                mma_tf32(acc[nt], ah[0], ah[1], ah[2], ah[3], bl[0], bl[1]);
                mma_tf32(acc[nt], al[0], al[1], al[2], al[3], bh[0], bh[1]);
            }
        }
    }

    float inv0 = 1.f / l_i[0], inv1 = 1.f / l_i[1];
    size_t o0 = ((size_t)((b * NS + q0 + mbase + r) * NH + h)) * NVH;
    size_t o1 = ((size_t)((b * NS + q0 + mbase + r + 8) * NH + h)) * NVH;
    #pragma unroll
    for (int nt = 0; nt < 16; nt++) {
        int col = nt * 8 + 2 * cq;
        *(float2*)&out[o0 + col] = make_float2(f2tf_f(acc[nt][0] * inv0), f2tf_f(acc[nt][1] * inv0));
        *(float2*)&out[o1 + col] = make_float2(f2tf_f(acc[nt][2] * inv1), f2tf_f(acc[nt][3] * inv1));
    }
}

// ---------------- launch ----------------
extern "C" void kernel_launch(void* const* d_in, const int* in_sizes, int n_in,
                              void* d_out, int out_size)
{
    const float* X    = (const float*)d_in[0];
    const float* bf   = (const float*)d_in[1];
    const float* Wqd  = (const float*)d_in[2];
    const float* bqd  = (const float*)d_in[3];
    const float* gq   = (const float*)d_in[4];
    const float* Wqu  = (const float*)d_in[5];
    const float* bqu  = (const float*)d_in[6];
    const float* Wkv  = (const float*)d_in[7];
    const float* bkv  = (const float*)d_in[8];
    const float* gkv  = (const float*)d_in[9];
    const float* Wkvu = (const float*)d_in[10];
    const float* bkvu = (const float*)d_in[11];
    const float* Wo   = (const float*)d_in[12];
    const float* bo   = (const float*)d_in[13];
    const int*   stp  = (const int*)d_in[14];
    float* out = (float*)d_out;

    float *qd, *qdn, *q, *kv, *kvn, *kvu, *krot, *att;
    float *xtf, *wqd, *wqu, *wkv, *wkvu, *wo;
    cudaGetSymbolAddress((void**)&qd,   g_qd);
    cudaGetSymbolAddress((void**)&qdn,  g_qdn);
    cudaGetSymbolAddress((void**)&q,    g_q);
    cudaGetSymbolAddress((void**)&kv,   g_kv);
    cudaGetSymbolAddress((void**)&kvn,  g_kvn);
    cudaGetSymbolAddress((void**)&kvu,  g_kvu);
    cudaGetSymbolAddress((void**)&krot, g_krot);
    cudaGetSymbolAddress((void**)&att,  g_att);
    cudaGetSymbolAddress((void**)&xtf,  g_xtf);
    cudaGetSymbolAddress((void**)&wqd,  g_wqd);
    cudaGetSymbolAddress((void**)&wqu,  g_wqu);
    cudaGetSymbolAddress((void**)&wkv,  g_wkv);
    cudaGetSymbolAddress((void**)&wkvu, g_wkvu);
    cudaGetSymbolAddress((void**)&wo,   g_wo);

    cudaFuncSetAttribute(gemm_tf32, cudaFuncAttributeMaxDynamicSharedMemorySize, GSMEM);
    cudaFuncSetAttribute(gemm_dualN, cudaFuncAttributeMaxDynamicSharedMemorySize, GSMEM);
    cudaFuncSetAttribute(attn_tc_kernel, cudaFuncAttributeMaxDynamicSharedMemorySize, ATTN_SMEM);

    // pre-round inputs/weights to tf32
    tf32_round_kernel<<<(NM*ND/4 + 255)/256, 256>>>(X, xtf, NM*ND/4);
    tf32_round_kernel<<<(NQL*ND/4 + 255)/256, 256>>>(Wqd, wqd, NQL*ND/4);
    tf32_round_kernel<<<(NH*NQKH*NQL/4 + 255)/256, 256>>>(Wqu, wqu, NH*NQKH*NQL/4);
    tf32_round_kernel<<<((NKVL+NROPE)*ND/4 + 255)/256, 256>>>(Wkv, wkv, (NKVL+NROPE)*ND/4);
    tf32_round_kernel<<<(NH*(NNOPE+NVH)*NKVL/4 + 255)/256, 256>>>(Wkvu, wkvu, NH*(NNOPE+NVH)*NKVL/4);
    tf32_round_kernel<<<(ND*NH*NVH/4 + 255)/256, 256>>>(Wo, wo, ND*NH*NVH/4);

    // fused down-projections (same A, same K=2048): qd (N=1536, 12 tiles) + kv (N=576, 5 tiles)
    gemm_dualN<<<dim3(NQL/128 + 5, NM/128), 256, GSMEM>>>(
        xtf, wqd, bqd, qd, NQL, NQL/128,
        wkv, bkv, kv, NKVL+NROPE, ND);

    // q path
    rms_kernel<<<NM, 256>>>(qd, NQL, NQL, gq, qdn);
    gemm_tf32<<<dim3((NH*NQKH)/128, NM/128), 256, GSMEM>>>(qdn, wqu, bqu, q, NM, NH*NQKH, NQL);
    rope_q_kernel<<<(NM*NH*32)/256, 256>>>(q, bf);

    // kv path
    rms_kernel<<<NM, 256>>>(kv, NKVL+NROPE, NKVL, gkv, kvn);
    gemm_tf32<<<dim3((NH*(NNOPE+NVH))/128, NM/128), 256, GSMEM>>>(kvn, wkvu, bkvu, kvu, NM, NH*(NNOPE+NVH), NKVL);
    rope_k_kernel<<<(NM*32)/256, 256>>>(kv, bf, krot);

    // attention (tensor core)
    attn_tc_kernel<<<dim3(NS/128, NH, NB), 256, ATTN_SMEM>>>(q, kvu, krot, stp, att);

    // output projection -> d_out
    gemm_tf32<<<dim3(ND/128, NM/128), 256, GSMEM>>>(att, wo, bo, out, NM, ND, ND);
}

// round 15
// speedup vs baseline: 1.3295x; 1.2255x over previous
#include <cuda_runtime.h>
#include <cuda_fp16.h>
#include <cstdint>

// ---------------- problem constants ----------------
#define NB 4
#define NS 1024
#define ND 2048
#define NH 16
#define NQL 1536
#define NKVL 512
#define NNOPE 128
#define NROPE 64
#define NVH 128
#define NQKH 192
#define NM (NB*NS)          // 4096 token rows

// ---------------- scratch ----------------
__device__ float  g_qd  [NM*NQL];
__device__ __half g_qdn [NM*NQL];
__device__ float  g_q   [NM*NH*NQKH];
__device__ float  g_kv  [NM*(NKVL+NROPE)];
__device__ __half g_kvn [NM*NKVL];
__device__ float  g_kvu [NM*NH*(NNOPE+NVH)];
__device__ float  g_krot[NM*NROPE];
__device__ __half g_att [NM*NH*NVH];
// fp16 copies (GEMM operands)
__device__ __half g_xh  [NM*ND];
__device__ __half g_wqd [NQL*ND];
__device__ __half g_wqu [NH*NQKH*NQL];
__device__ __half g_wkv [(NKVL+NROPE)*ND];
__device__ __half g_wkvu[NH*(NNOPE+NVH)*NKVL];
__device__ __half g_wo  [ND*NH*NVH];

// ---------------- helpers ----------------
__device__ __forceinline__ uint32_t f2tf(float x) {
    uint32_t y;
    asm("cvt.rna.tf32.f32 %0, %1;" : "=r"(y) : "f"(x));
    return y;
}
__device__ __forceinline__ void split_tf(float x, uint32_t& hi, uint32_t& lo) {
    hi = f2tf(x);
    lo = f2tf(x - __uint_as_float(hi));
}
__device__ __forceinline__ void mma_tf32(float* c,
    uint32_t a0, uint32_t a1, uint32_t a2, uint32_t a3,
    uint32_t b0, uint32_t b1)
{
    asm volatile(
        "mma.sync.aligned.m16n8k8.row.col.f32.tf32.tf32.f32 "
        "{%0,%1,%2,%3}, {%4,%5,%6,%7}, {%8,%9}, {%0,%1,%2,%3};\n"
        : "+f"(c[0]), "+f"(c[1]), "+f"(c[2]), "+f"(c[3])
        : "r"(a0), "r"(a1), "r"(a2), "r"(a3), "r"(b0), "r"(b1));
}
__device__ __forceinline__ void mma_f16(float* c,
    uint32_t a0, uint32_t a1, uint32_t a2, uint32_t a3,
    uint32_t b0, uint32_t b1)
{
    asm volatile(
        "mma.sync.aligned.m16n8k16.row.col.f32.f16.f16.f32 "
        "{%0,%1,%2,%3}, {%4,%5,%6,%7}, {%8,%9}, {%0,%1,%2,%3};\n"
        : "+f"(c[0]), "+f"(c[1]), "+f"(c[2]), "+f"(c[3])
        : "r"(a0), "r"(a1), "r"(a2), "r"(a3), "r"(b0), "r"(b1));
}
__device__ __forceinline__ void cpasync16(uint32_t saddr, const void* g, uint32_t sz) {
    asm volatile("cp.async.cg.shared.global [%0], [%1], 16, %2;\n"
                 :: "r"(saddr), "l"(g), "r"(sz));
}

// ---------------- fp16 convert: out[i] = half(in[i]) ----------------
__global__ __launch_bounds__(256) void fp16_round_kernel(
    const float* __restrict__ in, __half* __restrict__ out, int n4)
{
    int i = blockIdx.x * 256 + threadIdx.x;
    if (i < n4) {
        float4 v = ((const float4*)in)[i];
        __half2 h0 = __floats2half2_rn(v.x, v.y);
        __half2 h1 = __floats2half2_rn(v.z, v.w);
        ((__half2*)out)[i * 2]     = h0;
        ((__half2*)out)[i * 2 + 1] = h1;
    }
}

// ---------------- fp16 GEMM body: C[M,N]=A@W^T+bias, cp.async 2-stage ----------------
// smem rows: 32 halfs data + pad -> TPADH=40 (80B); frag u32 reads conflict-free.
#define TPADH 40
#define GSMEM (2 * 2 * 128 * TPADH * 2)   // 40 KB

__device__ __forceinline__ void gemm_body(
    const __half* __restrict__ A, const __half* __restrict__ W,
    const float* __restrict__ bias, float* __restrict__ C,
    int N, int K, int m0, int n0, __half* sm)
{
    __half* AsF = sm;
    __half* BsF = sm + 2 * 128 * TPADH;

    int tid = threadIdx.x;
    int lane = tid & 31, warp = tid >> 5;
    int mbase = (warp & 1) * 64;
    int nbase = (warp >> 1) * 32;
    int r = lane >> 2, cq = lane & 3;

    uint32_t aBase = (uint32_t)__cvta_generic_to_shared(AsF);
    uint32_t bBase = (uint32_t)__cvta_generic_to_shared(BsF);

    float acc[4][4][4];
    #pragma unroll
    for (int mt = 0; mt < 4; mt++)
        #pragma unroll
        for (int nt = 0; nt < 4; nt++)
            #pragma unroll
            for (int i = 0; i < 4; i++) acc[mt][nt][i] = 0.f;

    // per stage: 128 rows x 64B = 512 chunks of 16B per operand -> 2/thread
    auto issue_stage = [&](int s, int k0) {
        uint32_t so = (uint32_t)(s * 128 * TPADH) * 2u;
        #pragma unroll
        for (int j = 0; j < 2; j++) {
            int i = tid + (j << 8);
            int row = i >> 2, ch = i & 3;
            cpasync16(aBase + so + (uint32_t)(row * TPADH * 2 + ch * 16),
                      &A[(size_t)(m0 + row) * K + k0 + ch * 8], 16u);
        }
        #pragma unroll
        for (int j = 0; j < 2; j++) {
            int i = tid + (j << 8);
            int row = i >> 2, ch = i & 3;
            int nrow = n0 + row;
            const __half* gp = &W[(size_t)(nrow < N ? nrow : 0) * K + k0 + ch * 8];
            cpasync16(bBase + so + (uint32_t)(row * TPADH * 2 + ch * 16),
                      gp, nrow < N ? 16u : 0u);
        }
    };

    int nk = K >> 5;
    issue_stage(0, 0);
    asm volatile("cp.async.commit_group;\n");

    for (int kt = 0; kt < nk; kt++) {
        int cur = kt & 1;
        if (kt + 1 < nk) {
            issue_stage(cur ^ 1, (kt + 1) << 5);
            asm volatile("cp.async.commit_group;\n");
            asm volatile("cp.async.wait_group 1;\n");
        } else {
            asm volatile("cp.async.wait_group 0;\n");
        }
        __syncthreads();

        const __half* Ac = AsF + cur * 128 * TPADH;
        const __half* Bc = BsF + cur * 128 * TPADH;
        #pragma unroll
        for (int ks = 0; ks < 32; ks += 16) {
            uint32_t a[4][4], b[4][2];
            #pragma unroll
            for (int mt = 0; mt < 4; mt++) {
                int row = mbase + mt * 16 + r;
                a[mt][0] = *(const uint32_t*)&Ac[row * TPADH + ks + 2 * cq];
                a[mt][1] = *(const uint32_t*)&Ac[(row + 8) * TPADH + ks + 2 * cq];
                a[mt][2] = *(const uint32_t*)&Ac[row * TPADH + ks + 2 * cq + 8];
                a[mt][3] = *(const uint32_t*)&Ac[(row + 8) * TPADH + ks + 2 * cq + 8];
            }
            #pragma unroll
            for (int nt = 0; nt < 4; nt++) {
                int ncol = nbase + nt * 8 + r;
                b[nt][0] = *(const uint32_t*)&Bc[ncol * TPADH + ks + 2 * cq];
                b[nt][1] = *(const uint32_t*)&Bc[ncol * TPADH + ks + 2 * cq + 8];
            }
            #pragma unroll
            for (int mt = 0; mt < 4; mt++)
                #pragma unroll
                for (int nt = 0; nt < 4; nt++)
                    mma_f16(acc[mt][nt], a[mt][0], a[mt][1], a[mt][2], a[mt][3],
                            b[nt][0], b[nt][1]);
        }
        __syncthreads();
    }

    #pragma unroll
    for (int mt = 0; mt < 4; mt++) {
        #pragma unroll
        for (int nt = 0; nt < 4; nt++) {
            int row = m0 + mbase + mt * 16 + r;
            int col = n0 + nbase + nt * 8 + 2 * cq;
            if (col < N) {
                float b0 = __ldg(&bias[col]), b1 = __ldg(&bias[col + 1]);
                C[(size_t)row * N + col]           = acc[mt][nt][0] + b0;
                C[(size_t)row * N + col + 1]       = acc[mt][nt][1] + b1;
                C[(size_t)(row + 8) * N + col]     = acc[mt][nt][2] + b0;
                C[(size_t)(row + 8) * N + col + 1] = acc[mt][nt][3] + b1;
            }
        }
    }
}

__global__ __launch_bounds__(256) void gemm_h(
    const __half* __restrict__ A, const __half* __restrict__ W,
    const float* __restrict__ bias, float* __restrict__ C,
    int M, int N, int K)
{
    extern __shared__ __half smh[];
    gemm_body(A, W, bias, C, N, K, blockIdx.y << 7, blockIdx.x << 7, smh);
}

// dual-N: two outputs sharing same A and same K (down-projection pair)
__global__ __launch_bounds__(256) void gemm_dualN(
    const __half* __restrict__ A,
    const __half* __restrict__ W1, const float* __restrict__ b1,
    float* __restrict__ C1, int N1, int nx1,
    const __half* __restrict__ W2, const float* __restrict__ b2,
    float* __restrict__ C2, int N2, int K)
{
    extern __shared__ __half smh[];
    int bx = blockIdx.x;
    if (bx < nx1)
        gemm_body(A, W1, b1, C1, N1, K, blockIdx.y << 7, bx << 7, smh);
    else
        gemm_body(A, W2, b2, C2, N2, K, blockIdx.y << 7, (bx - nx1) << 7, smh);
}

// ---------------- RMS norm (fp16 output: feeds GEMM only) ----------------
__global__ __launch_bounds__(256) void rms_kernel(
    const float* __restrict__ in, int inStride, int W,
    const float* __restrict__ g, __half* __restrict__ out)
{
    int row = blockIdx.x;
    const float* x = in + (size_t)row * inStride;
    float s = 0.f;
    for (int i = threadIdx.x; i < W; i += 256) { float v = x[i]; s += v * v; }
    #pragma unroll
    for (int off = 16; off; off >>= 1) s += __shfl_xor_sync(0xffffffffu, s, off);
    __shared__ float red[8];
    int w = threadIdx.x >> 5;
    if ((threadIdx.x & 31) == 0) red[w] = s;
    __syncthreads();
    if (w == 0) {
        float v = (threadIdx.x < 8) ? red[threadIdx.x] : 0.f;
        #pragma unroll
        for (int off = 4; off; off >>= 1) v += __shfl_xor_sync(0xffffffffu, v, off);
        if (threadIdx.x == 0) red[0] = v;
    }
    __syncthreads();
    float inv = rsqrtf(red[0] / (float)W + 1e-6f);
    for (int i = threadIdx.x; i < W; i += 256)
        out[(size_t)row * W + i] = __float2half_rn(x[i] * inv * g[i]);
}

// ---------------- RoPE q ----------------
__global__ __launch_bounds__(256) void rope_q_kernel(
    float* __restrict__ q, const float* __restrict__ bf)
{
    int idx = blockIdx.x * 256 + threadIdx.x;
    int j = idx & 31;
    int h = (idx >> 5) & 15;
    int s = (idx >> 9) & 1023;
    int b = idx >> 19;
    float ang = bf[s * 64 + j];
    float c = cosf(ang), sn = sinf(ang);
    float* p = q + ((size_t)((b * NS + s) * NH + h)) * NQKH + NNOPE;
    float x1 = p[j], x2 = p[j + 32];
    p[j]      = x1 * c - x2 * sn;
    p[j + 32] = x2 * c + x1 * sn;
}

// ---------------- RoPE k ----------------
__global__ __launch_bounds__(256) void rope_k_kernel(
    const float* __restrict__ kv, const float* __restrict__ bf,
    float* __restrict__ krot)
{
    int idx = blockIdx.x * 256 + threadIdx.x;
    int j = idx & 31;
    int row = idx >> 5;
    int s = row & 1023;
    float ang = bf[s * 64 + j];
    float c = cosf(ang), sn = sinf(ang);
    float x1 = kv[(size_t)row * (NKVL + NROPE) + NKVL + j];
    float x2 = kv[(size_t)row * (NKVL + NROPE) + NKVL + 32 + j];
    krot[(size_t)row * 64 + j]      = x1 * c - x2 * sn;
    krot[(size_t)row * 64 + 32 + j] = x2 * c + x1 * sn;
}

// ---------------- tensor-core flash attention (3xTF32 = fp32 accuracy) ----------------
// output stored fp16 (feeds final GEMM only)
#define QPAD 196
#define KPAD 196
#define VPAD 136
#define PPAD 68
#define ATTN_SMEM ((128*QPAD + 64*KPAD + 64*VPAD + 128*PPAD) * 4)

__global__ __launch_bounds__(256) void attn_tc_kernel(
    const float* __restrict__ q, const float* __restrict__ kvu,
    const float* __restrict__ krot, const int* __restrict__ startp,
    __half* __restrict__ out)
{
    extern __shared__ float sm[];
    float* Qs = sm;
    float* Ks = Qs + 128 * QPAD;
    float* Vs = Ks + 64 * KPAD;
    float* Ps = Vs + 64 * VPAD;

    int qt = blockIdx.x, h = blockIdx.y, b = blockIdx.z;
    int q0 = qt << 7;
    int start = *startp;
    int tid = threadIdx.x, lane = tid & 31, warp = tid >> 5;
    int r = lane >> 2, cq = lane & 3;
    int mbase = warp << 4;
    const float scale = rsqrtf((float)NQKH);

    for (int p = tid * 4; p < 128 * 192; p += 1024) {
        int row = p / 192, d = p % 192;
        float4 v = *(const float4*)&q[((size_t)((b * NS + q0 + row) * NH + h)) * NQKH + d];
        v.x *= scale; v.y *= scale; v.z *= scale; v.w *= scale;
        *(float4*)&Qs[row * QPAD + d] = v;
    }

    float m_i[2] = {-1e30f, -1e30f}, l_i[2] = {0.f, 0.f};
    float acc[16][4];
    #pragma unroll
    for (int nt = 0; nt < 16; nt++)
        #pragma unroll
        for (int i = 0; i < 4; i++) acc[nt][i] = 0.f;

    int kmax = q0 + 128 + start; if (kmax > NS) kmax = NS;
    int nch = (kmax + 63) >> 6;
    int qrow0 = q0 + mbase + r;

    for (int c = 0; c < nch; c++) {
        int k0 = c << 6;
        __syncthreads();
        for (int p = tid * 4; p < 64 * 192; p += 1024) {
            int row = p / 192, d = p % 192;
            int grow = b * NS + k0 + row;
            float4 v;
            if (d < 128) v = *(const float4*)&kvu[((size_t)grow * NH + h) * 256 + d];
            else         v = *(const float4*)&krot[(size_t)grow * 64 + (d - 128)];
            *(float4*)&Ks[row * KPAD + d] = v;
        }
        for (int p = tid * 4; p < 64 * 128; p += 1024) {
            int row = p >> 7, d = p & 127;
            float4 v = *(const float4*)&kvu[((size_t)(b * NS + k0 + row) * NH + h) * 256 + 128 + d];
            *(float4*)&Vs[row * VPAD + d] = v;
        }
        __syncthreads();

        float s_acc[8][4];
        #pragma unroll
        for (int nt = 0; nt < 8; nt++)
            #pragma unroll
            for (int i = 0; i < 4; i++) s_acc[nt][i] = 0.f;

        #pragma unroll 4
        for (int kt = 0; kt < 24; kt++) {
            int ko = kt << 3;
            uint32_t ah[4], al[4];
            split_tf(Qs[(mbase + r) * QPAD + ko + cq],         ah[0], al[0]);
            split_tf(Qs[(mbase + r + 8) * QPAD + ko + cq],     ah[1], al[1]);
            split_tf(Qs[(mbase + r) * QPAD + ko + cq + 4],     ah[2], al[2]);
            split_tf(Qs[(mbase + r + 8) * QPAD + ko + cq + 4], ah[3], al[3]);
            #pragma unroll
            for (int nt = 0; nt < 8; nt++) {
                uint32_t bh[2], bl[2];
                split_tf(Ks[(nt * 8 + r) * KPAD + ko + cq],     bh[0], bl[0]);
                split_tf(Ks[(nt * 8 + r) * KPAD + ko + cq + 4], bh[1], bl[1]);
                mma_tf32(s_acc[nt], ah[0], ah[1], ah[2], ah[3], bh[0], bh[1]);
                mma_tf32(s_acc[nt], ah[0], ah[1], ah[2], ah[3], bl[0], bl[1]);
                mma_tf32(s_acc[nt], al[0], al[1], al[2], al[3], bh[0], bh[1]);
            }
        }

        #pragma unroll
        for (int nt = 0; nt < 8; nt++) {
            int col = k0 + nt * 8 + 2 * cq;
            if (col     > qrow0 + start)     s_acc[nt][0] = -1e30f;
            if (col + 1 > qrow0 + start)     s_acc[nt][1] = -1e30f;
            if (col     > qrow0 + 8 + start) s_acc[nt][2] = -1e30f;
            if (col + 1 > qrow0 + 8 + start) s_acc[nt][3] = -1e30f;
        }
        float mx0 = -1e30f, mx1 = -1e30f;
        #pragma unroll
        for (int nt = 0; nt < 8; nt++) {
            mx0 = fmaxf(mx0, fmaxf(s_acc[nt][0], s_acc[nt][1]));
            mx1 = fmaxf(mx1, fmaxf(s_acc[nt][2], s_acc[nt][3]));
        }
        mx0 = fmaxf(mx0, __shfl_xor_sync(0xffffffffu, mx0, 1));
        mx0 = fmaxf(mx0, __shfl_xor_sync(0xffffffffu, mx0, 2));
        mx1 = fmaxf(mx1, __shfl_xor_sync(0xffffffffu, mx1, 1));
        mx1 = fmaxf(mx1, __shfl_xor_sync(0xffffffffu, mx1, 2));

        float mn0 = fmaxf(m_i[0], mx0), mn1 = fmaxf(m_i[1], mx1);
        float fac0 = __expf(m_i[0] - mn0), fac1 = __expf(m_i[1] - mn1);
        float sum0 = 0.f, sum1 = 0.f;
        #pragma unroll
        for (int nt = 0; nt < 8; nt++) {
            s_acc[nt][0] = __expf(s_acc[nt][0] - mn0);
            s_acc[nt][1] = __expf(s_acc[nt][1] - mn0);
            s_acc[nt][2] = __expf(s_acc[nt][2] - mn1);
            s_acc[nt][3] = __expf(s_acc[nt][3] - mn1);
            sum0 += s_acc[nt][0] + s_acc[nt][1];
            sum1 += s_acc[nt][2] + s_acc[nt][3];
        }
        sum0 += __shfl_xor_sync(0xffffffffu, sum0, 1);
        sum0 += __shfl_xor_sync(0xffffffffu, sum0, 2);
        sum1 += __shfl_xor_sync(0xffffffffu, sum1, 1);
        sum1 += __shfl_xor_sync(0xffffffffu, sum1, 2);
        l_i[0] = l_i[0] * fac0 + sum0;
        l_i[1] = l_i[1] * fac1 + sum1;
        m_i[0] = mn0; m_i[1] = mn1;
        #pragma unroll
        for (int nt = 0; nt < 16; nt++) {
            acc[nt][0] *= fac0; acc[nt][1] *= fac0;
            acc[nt][2] *= fac1; acc[nt][3] *= fac1;
        }
        #pragma unroll
        for (int nt = 0; nt < 8; nt++) {
            int colo = nt * 8 + 2 * cq;
            Ps[(mbase + r) * PPAD + colo]         = s_acc[nt][0];
            Ps[(mbase + r) * PPAD + colo + 1]     = s_acc[nt][1];
            Ps[(mbase + r + 8) * PPAD + colo]     = s_acc[nt][2];
            Ps[(mbase + r + 8) * PPAD + colo + 1] = s_acc[nt][3];
        }
        __syncwarp();

        #pragma unroll
        for (int kt = 0; kt < 8; kt++) {
            int ko = kt << 3;
            uint32_t ah[4], al[4];
            split_tf(Ps[(mbase + r) * PPAD + ko + cq],         ah[0], al[0]);
            split_tf(Ps[(mbase + r + 8) * PPAD + ko + cq],     ah[1], al[1]);
            split_tf(Ps[(mbase + r) * PPAD + ko + cq + 4],     ah[2], al[2]);
            split_tf(Ps[(mbase + r + 8) * PPAD + ko + cq + 4], ah[3], al[3]);
            #pragma unroll
            for (int nt = 0; nt < 16; nt++) {
                uint32_t bh[2], bl[2];
                split_tf(Vs[(ko + cq) * VPAD + nt * 8 + r],     bh[0], bl[0]);
                split_tf(Vs[(ko + cq + 4) * VPAD + nt * 8 + r], bh[1], bl[1]);
                mma_tf32(acc[nt], ah[0], ah[1], ah[2], ah[3], bh[0], bh[1]);
                mma_tf32(acc[nt], ah[0], ah[1], ah[2], ah[3], bl[0], bl[1]);
                mma_tf32(acc[nt], al[0], al[1], al[2], al[3], bh[0], bh[1]);
            }
        }
    }

    float inv0 = 1.f / l_i[0], inv1 = 1.f / l_i[1];
    size_t o0 = ((size_t)((b * NS + q0 + mbase + r) * NH + h)) * NVH;
    size_t o1 = ((size_t)((b * NS + q0 + mbase + r + 8) * NH + h)) * NVH;
    #pragma unroll
    for (int nt = 0; nt < 16; nt++) {
        int col = nt * 8 + 2 * cq;
        *(__half2*)&out[o0 + col] = __floats2half2_rn(acc[nt][0] * inv0, acc[nt][1] * inv0);
        *(__half2*)&out[o1 + col] = __floats2half2_rn(acc[nt][2] * inv1, acc[nt][3] * inv1);
    }
}

// ---------------- launch ----------------
extern "C" void kernel_launch(void* const* d_in, const int* in_sizes, int n_in,
                              void* d_out, int out_size)
{
    const float* X    = (const float*)d_in[0];
    const float* bf   = (const float*)d_in[1];
    const float* Wqd  = (const float*)d_in[2];
    const float* bqd  = (const float*)d_in[3];
    const float* gq   = (const float*)d_in[4];
    const float* Wqu  = (const float*)d_in[5];
    const float* bqu  = (const float*)d_in[6];
    const float* Wkv  = (const float*)d_in[7];
    const float* bkv  = (const float*)d_in[8];
    const float* gkv  = (const float*)d_in[9];
    const float* Wkvu = (const float*)d_in[10];
    const float* bkvu = (const float*)d_in[11];
    const float* Wo   = (const float*)d_in[12];
    const float* bo   = (const float*)d_in[13];
    const int*   stp  = (const int*)d_in[14];
    float* out = (float*)d_out;

    float *qd, *q, *kv, *kvu, *krot;
    __half *qdn, *kvn, *att, *xh, *wqd, *wqu, *wkv, *wkvu, *wo;
    cudaGetSymbolAddress((void**)&qd,   g_qd);
    cudaGetSymbolAddress((void**)&qdn,  g_qdn);
    cudaGetSymbolAddress((void**)&q,    g_q);
    cudaGetSymbolAddress((void**)&kv,   g_kv);
    cudaGetSymbolAddress((void**)&kvn,  g_kvn);
    cudaGetSymbolAddress((void**)&kvu,  g_kvu);
    cudaGetSymbolAddress((void**)&krot, g_krot);
    cudaGetSymbolAddress((void**)&att,  g_att);
    cudaGetSymbolAddress((void**)&xh,   g_xh);
    cudaGetSymbolAddress((void**)&wqd,  g_wqd);
    cudaGetSymbolAddress((void**)&wqu,  g_wqu);
    cudaGetSymbolAddress((void**)&wkv,  g_wkv);
    cudaGetSymbolAddress((void**)&wkvu, g_wkvu);
    cudaGetSymbolAddress((void**)&wo,   g_wo);

    cudaFuncSetAttribute(gemm_h, cudaFuncAttributeMaxDynamicSharedMemorySize, GSMEM);
    cudaFuncSetAttribute(gemm_dualN, cudaFuncAttributeMaxDynamicSharedMemorySize, GSMEM);
    cudaFuncSetAttribute(attn_tc_kernel, cudaFuncAttributeMaxDynamicSharedMemorySize, ATTN_SMEM);

    // convert X + weights to fp16
    fp16_round_kernel<<<(NM*ND/4 + 255)/256, 256>>>(X, xh, NM*ND/4);
    fp16_round_kernel<<<(NQL*ND/4 + 255)/256, 256>>>(Wqd, wqd, NQL*ND/4);
    fp16_round_kernel<<<(NH*NQKH*NQL/4 + 255)/256, 256>>>(Wqu, wqu, NH*NQKH*NQL/4);
    fp16_round_kernel<<<((NKVL+NROPE)*ND/4 + 255)/256, 256>>>(Wkv, wkv, (NKVL+NROPE)*ND/4);
    fp16_round_kernel<<<(NH*(NNOPE+NVH)*NKVL/4 + 255)/256, 256>>>(Wkvu, wkvu, NH*(NNOPE+NVH)*NKVL/4);
    fp16_round_kernel<<<(ND*NH*NVH/4 + 255)/256, 256>>>(Wo, wo, ND*NH*NVH/4);

    // fused down-projections (same A, same K=2048)
    gemm_dualN<<<dim3(NQL/128 + 5, NM/128), 256, GSMEM>>>(
        xh, wqd, bqd, qd, NQL, NQL/128,
        wkv, bkv, kv, NKVL+NROPE, ND);

    // q path
    rms_kernel<<<NM, 256>>>(qd, NQL, NQL, gq, qdn);
    gemm_h<<<dim3((NH*NQKH)/128, NM/128), 256, GSMEM>>>(qdn, wqu, bqu, q, NM, NH*NQKH, NQL);
    rope_q_kernel<<<(NM*NH*32)/256, 256>>>(q, bf);

    // kv path
    rms_kernel<<<NM, 256>>>(kv, NKVL+NROPE, NKVL, gkv, kvn);
    gemm_h<<<dim3((NH*(NNOPE+NVH))/128, NM/128), 256, GSMEM>>>(kvn, wkvu, bkvu, kvu, NM, NH*(NNOPE+NVH), NKVL);
    rope_k_kernel<<<(NM*32)/256, 256>>>(kv, bf, krot);

    // attention (tensor core, fp32-accurate)
    attn_tc_kernel<<<dim3(NS/128, NH, NB), 256, ATTN_SMEM>>>(q, kvu, krot, stp, att);

    // output projection -> d_out
    gemm_h<<<dim3(ND/128, NM/128), 256, GSMEM>>>(att, wo, bo, out, NM, ND, ND);
}